// round 9
// baseline (speedup 1.0000x reference)
#include <cuda_runtime.h>
#include <math.h>

// Problem constants
#define Gn     4096
#define Bn     2
#define NH     32
#define NIN    8
#define TI     64          // i rows per heavy block
#define JSPLIT 4           // j-range splits (partials reduced deterministically)
#define JRANGE (Gn / JSPLIT)  // 1024
#define CHUNK  32
#define C_ALPHA 0.005f
#define C_BETA  5e-5f
#define C_BNEPS 1e-5f

// Scratch (no cudaMalloc allowed)
__device__ __align__(16) float g_feat1[Bn * Gn * NH];
__device__ __align__(16) float g_feat2[Bn * Gn * NH];
__device__ __align__(16) float g_ssrc[Bn * Gn];
__device__ __align__(16) float g_sdst[Bn * Gn];
__device__ __align__(16) float g_psrc[Bn * JSPLIT * Gn * NH];   // recv_src partials
__device__ __align__(16) float g_pesum[Bn * JSPLIT * Gn];       // esum partials

__device__ __forceinline__ float elu1(float v) { return v > 0.f ? v : expm1f(v); }

// ---------------------------------------------------------------------------
// h = elu(x @ W_infer + b_infer)   [B,G,8] -> [B,G,32]
// ---------------------------------------------------------------------------
__global__ void k_infer(const float* __restrict__ x,
                        const float* __restrict__ W,
                        const float* __restrict__ bias) {
    int idx = blockIdx.x * blockDim.x + threadIdx.x;   // over B*G*NH
    int h  = idx & 31;
    int bg = idx >> 5;
    const float* xr = x + bg * NIN;
    float acc = bias[h];
#pragma unroll
    for (int k = 0; k < NIN; k++) acc += xr[k] * W[k * NH + h];
    g_feat1[idx] = elu1(acc);
}

// ---------------------------------------------------------------------------
// s_src[b,g] = feat . W_e[0:32],  s_dst[b,g] = feat . W_e[32:64] + b_e
// one warp per node
// ---------------------------------------------------------------------------
__global__ void k_scores(const float* __restrict__ feat,
                         const float* __restrict__ We,
                         const float* __restrict__ be) {
    int gidx = blockIdx.x * blockDim.x + threadIdx.x;
    int node = gidx >> 5;            // 0..B*G-1
    int lane = threadIdx.x & 31;
    float f = feat[node * NH + lane];
    float a = f * __ldg(&We[lane]);
    float d = f * __ldg(&We[32 + lane]);
#pragma unroll
    for (int o = 16; o > 0; o >>= 1) {
        a += __shfl_xor_sync(0xffffffffu, a, o);
        d += __shfl_xor_sync(0xffffffffu, d, o);
    }
    if (lane == 0) {
        g_ssrc[node] = a;
        g_sdst[node] = d + be[0];
    }
}

// ---------------------------------------------------------------------------
// Heavy kernel: on-the-fly E tile construction + recv_src / esum accumulation
// grid = (G/TI, JSPLIT, B), block = 256
// ---------------------------------------------------------------------------
__global__ __launch_bounds__(256) void k_heavy(const float* __restrict__ feat,
                                               const float* __restrict__ adj,
                                               float coef) {
    __shared__ __align__(16) float x_s[CHUNK][NH];   // 32 x 32 floats (4 KB)
    __shared__ __align__(16) float e_s[CHUNK][TI];   // 32 x 64 floats (8 KB)

    const int t     = threadIdx.x;
    const int b     = blockIdx.z;
    const int split = blockIdx.y;
    const int i0    = blockIdx.x * TI;
    const int jbase = split * JRANGE;

    // E-construction mapping: 4 threads per i row, 8 consecutive j each (coalesced adj)
    const int ci  = t >> 2;          // 0..63  (row within tile)
    const int cjg = (t & 3) * 8;     // 0,8,16,24

    // main-loop mapping: 4i x 2h register tile per thread
    const int ty = t >> 4;           // 0..15 -> i group of 4
    const int tx = t & 15;           // 0..15 -> h pair

    const float sd = g_sdst[b * Gn + i0 + ci];
    const float* __restrict__ featb = feat + (size_t)b * Gn * NH;
    const float* __restrict__ ssb   = g_ssrc + b * Gn;
    const float* __restrict__ adjr  = adj + (size_t)(i0 + ci) * Gn;

    float acc[4][2];
#pragma unroll
    for (int r = 0; r < 4; r++) { acc[r][0] = 0.f; acc[r][1] = 0.f; }
    float esum0 = 0.f, esum1 = 0.f;

    const int xrow = t >> 3;         // staging: 32 rows x 8 float4
    const int xc4  = (t & 7) * 4;

    for (int jc = 0; jc < JRANGE; jc += CHUNK) {
        const int j0 = jbase + jc;
        __syncthreads();   // previous chunk consumers done

        // stage x chunk [32 j x 32 h]
        {
            const float4 v = *reinterpret_cast<const float4*>(featb + (size_t)(j0 + xrow) * NH + xc4);
            *reinterpret_cast<float4*>(&x_s[xrow][xc4]) = v;
        }
        // construct e tile: e[jj][i] = sigmoid(sd_i + ss_j) * w(adj)
        {
            const float4 a0 = *reinterpret_cast<const float4*>(adjr + j0 + cjg);
            const float4 a1 = *reinterpret_cast<const float4*>(adjr + j0 + cjg + 4);
            const float4 s0 = *reinterpret_cast<const float4*>(ssb + j0 + cjg);
            const float4 s1 = *reinterpret_cast<const float4*>(ssb + j0 + cjg + 4);
            float av[8] = {a0.x, a0.y, a0.z, a0.w, a1.x, a1.y, a1.z, a1.w};
            float sv[8] = {s0.x, s0.y, s0.z, s0.w, s1.x, s1.y, s1.z, s1.w};
#pragma unroll
            for (int k = 0; k < 8; k++) {
                float lg  = sd + sv[k];
                float sig = __fdividef(1.f, 1.f + __expf(-lg));
                float w   = (av[k] == 0.f) ? coef : av[k];  // adj + coef*(adj==0)
                e_s[cjg + k][ci] = sig * w;
            }
        }
        __syncthreads();   // tiles ready

        // deterministic esum: thread t<64 owns row i0+t
        if (t < 64) {
            float s0 = 0.f, s1 = 0.f;
#pragma unroll
            for (int jj = 0; jj < CHUNK; jj += 2) {
                s0 += e_s[jj][t];
                s1 += e_s[jj + 1][t];
            }
            esum0 += s0;
            esum1 += s1;
        }

        // main accumulation: acc[i'][h'] += e[jj][i'] * x[jj][h']
#pragma unroll
        for (int jj = 0; jj < CHUNK; jj++) {
            const float4 e4 = *reinterpret_cast<const float4*>(&e_s[jj][ty * 4]);
            const float2 x2 = *reinterpret_cast<const float2*>(&x_s[jj][tx * 2]);
            acc[0][0] += e4.x * x2.x;  acc[0][1] += e4.x * x2.y;
            acc[1][0] += e4.y * x2.x;  acc[1][1] += e4.y * x2.y;
            acc[2][0] += e4.z * x2.x;  acc[2][1] += e4.z * x2.y;
            acc[3][0] += e4.w * x2.x;  acc[3][1] += e4.w * x2.y;
        }
    }

    // write partials
    float* ps = g_psrc + (size_t)(b * JSPLIT + split) * Gn * NH;
#pragma unroll
    for (int r = 0; r < 4; r++) {
        float2 v; v.x = acc[r][0]; v.y = acc[r][1];
        *reinterpret_cast<float2*>(ps + (size_t)(i0 + ty * 4 + r) * NH + tx * 2) = v;
    }
    if (t < 64) g_pesum[(b * JSPLIT + split) * Gn + i0 + t] = esum0 + esum1;
}

// ---------------------------------------------------------------------------
// Finish: reduce partials (fixed order), recv_dst = x*esum, then fused
//   recv2 = elu([recv_src, recv_dst] @ W_n + b_n)
//   out   = elu([recv2, x] @ W_m + b_m)
// one warp per node, weights staged in smem
// ---------------------------------------------------------------------------
__global__ __launch_bounds__(256) void k_finish(const float* __restrict__ feat,
                                                const float* __restrict__ Wn,
                                                const float* __restrict__ bn,
                                                const float* __restrict__ Wm,
                                                const float* __restrict__ bm,
                                                float* __restrict__ out) {
    __shared__ float sWn[64 * 32];
    __shared__ float sWm[64 * 32];
    __shared__ float sbn[32], sbm[32];
    __shared__ float buf[8][64];

    const int t = threadIdx.x;
    for (int k = t; k < 2048; k += 256) { sWn[k] = Wn[k]; sWm[k] = Wm[k]; }
    if (t < 32) { sbn[t] = bn[t]; sbm[t] = bm[t]; }
    __syncthreads();

    const int w    = t >> 5;
    const int lane = t & 31;
    const int node = blockIdx.x * 8 + w;   // 0..B*G-1
    const int b    = node >> 12;
    const int i    = node & (Gn - 1);

    float rs = 0.f;
#pragma unroll
    for (int s = 0; s < JSPLIT; s++)
        rs += g_psrc[((size_t)(b * JSPLIT + s) * Gn + i) * NH + lane];
    float es = 0.f;
#pragma unroll
    for (int s = 0; s < JSPLIT; s++)
        es += g_pesum[(b * JSPLIT + s) * Gn + i];
    const float xv = feat[(size_t)node * NH + lane];

    buf[w][lane]      = rs;        // recv_src
    buf[w][32 + lane] = xv * es;   // recv_dst
    __syncwarp();

    float acc = sbn[lane];
#pragma unroll
    for (int k = 0; k < 64; k++) acc += buf[w][k] * sWn[k * 32 + lane];
    acc = elu1(acc);
    __syncwarp();

    buf[w][lane]      = acc;   // recv2
    buf[w][32 + lane] = xv;    // x
    __syncwarp();

    float acc2 = sbm[lane];
#pragma unroll
    for (int k = 0; k < 64; k++) acc2 += buf[w][k] * sWm[k * 32 + lane];
    out[(size_t)node * NH + lane] = elu1(acc2);
}

// ---------------------------------------------------------------------------
// BatchNorm over (batch, feature) per gene, in-place on g_feat2
// one warp per gene (64 values)
// ---------------------------------------------------------------------------
__global__ void k_bn(const float* __restrict__ gamma,
                     const float* __restrict__ beta) {
    const int t    = threadIdx.x;
    const int w    = t >> 5;
    const int lane = t & 31;
    const int g    = blockIdx.x * 8 + w;

    float v0 = g_feat2[(size_t)(0 * Gn + g) * NH + lane];
    float v1 = g_feat2[(size_t)(1 * Gn + g) * NH + lane];

    float s = v0 + v1;
#pragma unroll
    for (int o = 16; o > 0; o >>= 1) s += __shfl_xor_sync(0xffffffffu, s, o);
    const float mu = s * (1.f / 64.f);

    const float d0 = v0 - mu, d1 = v1 - mu;
    float q = d0 * d0 + d1 * d1;
#pragma unroll
    for (int o = 16; o > 0; o >>= 1) q += __shfl_xor_sync(0xffffffffu, q, o);

    const float scale = rsqrtf(q * (1.f / 64.f) + C_BNEPS) * gamma[g];
    const float bb = beta[g];
    g_feat2[(size_t)(0 * Gn + g) * NH + lane] = d0 * scale + bb;
    g_feat2[(size_t)(1 * Gn + g) * NH + lane] = d1 * scale + bb;
}

// ---------------------------------------------------------------------------
extern "C" void kernel_launch(void* const* d_in, const int* in_sizes, int n_in,
                              void* d_out, int out_size) {
    const float* x   = (const float*)d_in[0];
    const float* e1  = (const float*)d_in[1];
    const float* e2  = (const float*)d_in[2];
    const float* Wi  = (const float*)d_in[3];
    const float* bi  = (const float*)d_in[4];
    const float* We1 = (const float*)d_in[5];
    const float* be1 = (const float*)d_in[6];
    const float* We2 = (const float*)d_in[7];
    const float* be2 = (const float*)d_in[8];
    const float* Wn1 = (const float*)d_in[9];
    const float* bn1 = (const float*)d_in[10];
    const float* Wn2 = (const float*)d_in[11];
    const float* bn2 = (const float*)d_in[12];
    const float* Wm1 = (const float*)d_in[13];
    const float* bm1 = (const float*)d_in[14];
    const float* Wm2 = (const float*)d_in[15];
    const float* bm2 = (const float*)d_in[16];
    const float* gam = (const float*)d_in[17];
    const float* bet = (const float*)d_in[18];
    float* out = (float*)d_out;

    float* feat1 = nullptr;
    float* feat2 = nullptr;
    cudaGetSymbolAddress((void**)&feat1, g_feat1);   // host query, capture-safe
    cudaGetSymbolAddress((void**)&feat2, g_feat2);

    const dim3 hgrid(Gn / TI, JSPLIT, Bn);   // 64 x 4 x 2 = 512 blocks

    // h0 = elu(x @ W_infer + b)
    k_infer<<<(Bn * Gn * NH) / 256, 256>>>(x, Wi, bi);

    // message-passing block 1
    k_scores<<<(Bn * Gn * 32) / 256, 256>>>(feat1, We1, be1);
    k_heavy<<<hgrid, 256>>>(feat1, e1, C_ALPHA);
    k_finish<<<(Bn * Gn) / 8, 256>>>(feat1, Wn1, bn1, Wm1, bm1, feat2);

    // batchnorm (in place on feat2)
    k_bn<<<Gn / 8, 256>>>(gam, bet);

    // message-passing block 2
    k_scores<<<(Bn * Gn * 32) / 256, 256>>>(feat2, We2, be2);
    k_heavy<<<hgrid, 256>>>(feat2, e2, C_BETA);
    k_finish<<<(Bn * Gn) / 8, 256>>>(feat2, Wn2, bn2, Wm2, bm2, out);
}